// round 1
// baseline (speedup 1.0000x reference)
#include <cuda_runtime.h>
#include <cuda_bf16.h>
#include <math.h>

// Problem constants
// x:  [B=8, C=512, H=32, W=32] -> [8, 512, 1024]
// W*: [512, 512], b*: [512]
// heads = 8, head_dim = 64, N = 1024

#define BATCH 8
#define DIM 512
#define NPIX 1024
#define NH 8
#define HD 64

// Scratch (static __device__ globals: allocation-guard safe)
__device__ float g_Q[BATCH * DIM * NPIX];
__device__ float g_K[BATCH * DIM * NPIX];
__device__ float g_V[BATCH * DIM * NPIX];
__device__ float g_AO[BATCH * DIM * NPIX];

// ---------------------------------------------------------------------------
// GEMM: out[b][o][n] = (sum_c W[o][c] * X[b][c][n] + bias[o]) * scale (+ resid)
// M=512 (o), N=1024 (n), K=512 (c). Tiles: 128x128, BK=16. 256 threads, 8x8/thread.
// ---------------------------------------------------------------------------
__global__ __launch_bounds__(256, 2)
void gemm512(const float* __restrict__ W, const float* __restrict__ X,
             const float* __restrict__ bias, const float* __restrict__ resid,
             float* __restrict__ out, float scale)
{
    const int b  = blockIdx.z;
    const int m0 = blockIdx.y * 128;
    const int n0 = blockIdx.x * 128;

    const float* Xb   = X + (size_t)b * DIM * NPIX;
    float*       outb = out + (size_t)b * DIM * NPIX;
    const float* resb = resid ? resid + (size_t)b * DIM * NPIX : nullptr;

    __shared__ float As[16][132];   // [k][m], padded (132) to de-conflict transposed stores
    __shared__ float Bs[16][128];   // [k][n]

    const int tid = threadIdx.x;
    const int tx  = tid & 15;      // n sub-tile
    const int ty  = tid >> 4;      // m sub-tile

    float acc[8][8];
    #pragma unroll
    for (int i = 0; i < 8; i++)
        #pragma unroll
        for (int j = 0; j < 8; j++) acc[i][j] = 0.f;

    for (int k0 = 0; k0 < DIM; k0 += 16) {
        // Load W tile transposed: As[k][m] = W[(m0+m)*512 + k0+k]
        #pragma unroll
        for (int it = tid; it < 512; it += 256) {
            int m = it >> 2, kg = it & 3;
            float4 v = *(const float4*)&W[(size_t)(m0 + m) * DIM + k0 + kg * 4];
            As[kg * 4 + 0][m] = v.x;
            As[kg * 4 + 1][m] = v.y;
            As[kg * 4 + 2][m] = v.z;
            As[kg * 4 + 3][m] = v.w;
        }
        // Load X tile: Bs[k][n] = X[k0+k][n0+n]   (coalesced float4)
        #pragma unroll
        for (int it = tid; it < 512; it += 256) {
            int k = it >> 5, ng = it & 31;
            *(float4*)&Bs[k][ng * 4] =
                *(const float4*)&Xb[(size_t)(k0 + k) * NPIX + n0 + ng * 4];
        }
        __syncthreads();

        #pragma unroll
        for (int k = 0; k < 16; k++) {
            float a[8], bb[8];
            *(float4*)&a[0]  = *(const float4*)&As[k][ty * 8];
            *(float4*)&a[4]  = *(const float4*)&As[k][ty * 8 + 4];
            *(float4*)&bb[0] = *(const float4*)&Bs[k][tx * 8];
            *(float4*)&bb[4] = *(const float4*)&Bs[k][tx * 8 + 4];
            #pragma unroll
            for (int i = 0; i < 8; i++)
                #pragma unroll
                for (int j = 0; j < 8; j++)
                    acc[i][j] += a[i] * bb[j];
        }
        __syncthreads();
    }

    // Epilogue: bias, scale, optional residual; float4 stores
    #pragma unroll
    for (int i = 0; i < 8; i++) {
        int o = m0 + ty * 8 + i;
        float bv = bias[o];
        size_t rowoff = (size_t)o * NPIX + n0 + tx * 8;
        #pragma unroll
        for (int jg = 0; jg < 2; jg++) {
            float4 r;
            r.x = (acc[i][jg * 4 + 0] + bv) * scale;
            r.y = (acc[i][jg * 4 + 1] + bv) * scale;
            r.z = (acc[i][jg * 4 + 2] + bv) * scale;
            r.w = (acc[i][jg * 4 + 3] + bv) * scale;
            if (resb) {
                float4 xv = *(const float4*)&resb[rowoff + jg * 4];
                r.x += xv.x; r.y += xv.y; r.z += xv.z; r.w += xv.w;
            }
            *(float4*)&outb[rowoff + jg * 4] = r;
        }
    }
}

// ---------------------------------------------------------------------------
// Fused flash-style attention. Q,K,V: [B*NH, 64, 1024] (d-major, n contiguous).
// 1/sqrt(hd) already folded into Q. One block = 64 queries of one (b,h).
// Online softmax over 16 key tiles of 64. 48KB static smem exactly.
// ---------------------------------------------------------------------------
__global__ __launch_bounds__(256, 2)
void attn64(const float* __restrict__ Q, const float* __restrict__ K,
            const float* __restrict__ V, float* __restrict__ O)
{
    __shared__ float Qt[64][64];   // [d][i]
    __shared__ float KV[64][64];   // K phase: [d][j]; V phase: swizzled [j][d]
    __shared__ float Ps[64][64];   // [i][j]

    const int tid = threadIdx.x;
    const int tx  = tid & 15;      // j (gemm1) / d (gemm2) sub-tile
    const int ty  = tid >> 4;      // i sub-tile
    const int n0  = blockIdx.x * 64;

    const size_t base = ((size_t)blockIdx.z * NH + blockIdx.y) * (size_t)HD * NPIX;
    const float* Qp = Q + base;
    const float* Kp = K + base;
    const float* Vp = V + base;
    float*       Op = O + base;

    // Load Q tile [64d x 64i]
    #pragma unroll
    for (int it = tid; it < 1024; it += 256) {
        int d = it >> 4, ig = it & 15;
        *(float4*)&Qt[d][ig * 4] = *(const float4*)&Qp[(size_t)d * NPIX + n0 + ig * 4];
    }

    float m_i[4], l_i[4], Ot[4][4];
    #pragma unroll
    for (int ii = 0; ii < 4; ii++) {
        m_i[ii] = -1e30f;
        l_i[ii] = 0.f;
        #pragma unroll
        for (int dd = 0; dd < 4; dd++) Ot[ii][dd] = 0.f;
    }

    for (int kt = 0; kt < 16; kt++) {
        const int j0 = kt * 64;

        // Load K tile [64d x 64j]
        #pragma unroll
        for (int it = tid; it < 1024; it += 256) {
            int d = it >> 4, jg = it & 15;
            *(float4*)&KV[d][jg * 4] =
                *(const float4*)&Kp[(size_t)d * NPIX + j0 + jg * 4];
        }
        __syncthreads();   // also covers the Qt load on kt==0

        // GEMM1: S[i][j] = sum_d Qt[d][i] * K[d][j]
        float S[4][4];
        #pragma unroll
        for (int ii = 0; ii < 4; ii++)
            #pragma unroll
            for (int jj = 0; jj < 4; jj++) S[ii][jj] = 0.f;

        #pragma unroll 16
        for (int d = 0; d < 64; d++) {
            float4 q  = *(const float4*)&Qt[d][ty * 4];
            float4 kk = *(const float4*)&KV[d][tx * 4];
            float qa[4] = {q.x, q.y, q.z, q.w};
            float ka[4] = {kk.x, kk.y, kk.z, kk.w};
            #pragma unroll
            for (int ii = 0; ii < 4; ii++)
                #pragma unroll
                for (int jj = 0; jj < 4; jj++)
                    S[ii][jj] += qa[ii] * ka[jj];
        }

        // Online softmax per row i (rows owned by ty; reduce across 16 tx lanes)
        #pragma unroll
        for (int ii = 0; ii < 4; ii++) {
            float mx = fmaxf(fmaxf(S[ii][0], S[ii][1]), fmaxf(S[ii][2], S[ii][3]));
            #pragma unroll
            for (int o = 8; o >= 1; o >>= 1)
                mx = fmaxf(mx, __shfl_xor_sync(0xffffffffu, mx, o));
            float mn   = fmaxf(m_i[ii], mx);
            float corr = __expf(m_i[ii] - mn);
            m_i[ii] = mn;

            float4 p;
            p.x = __expf(S[ii][0] - mn);
            p.y = __expf(S[ii][1] - mn);
            p.z = __expf(S[ii][2] - mn);
            p.w = __expf(S[ii][3] - mn);
            *(float4*)&Ps[ty * 4 + ii][tx * 4] = p;

            float rs = p.x + p.y + p.z + p.w;
            #pragma unroll
            for (int o = 8; o >= 1; o >>= 1)
                rs += __shfl_xor_sync(0xffffffffu, rs, o);
            l_i[ii] = l_i[ii] * corr + rs;

            #pragma unroll
            for (int dd = 0; dd < 4; dd++) Ot[ii][dd] *= corr;
        }
        __syncthreads();   // all GEMM1 KV reads done; Ps fully written

        // Load V transposed with XOR swizzle: logical Vt[j][d] at
        // KV[j][ ((d>>2) ^ (j>>2)) & 15 ) * 4 + (d&3) ]
        #pragma unroll
        for (int it = tid; it < 1024; it += 256) {
            int d = it >> 4, jg = it & 15;
            float4 v = *(const float4*)&Vp[(size_t)d * NPIX + j0 + jg * 4];
            int dg = d >> 2, dm = d & 3;
            int pc = ((dg ^ jg) & 15) * 4 + dm;   // j>>2 == jg for these 4 j's
            float va[4] = {v.x, v.y, v.z, v.w};
            #pragma unroll
            for (int c = 0; c < 4; c++)
                KV[jg * 4 + c][pc] = va[c];
        }
        __syncthreads();

        // GEMM2: Ot[i][d] += sum_j Ps[i][j] * Vt[j][d]
        #pragma unroll
        for (int j4 = 0; j4 < 16; j4++) {
            int sw = ((tx ^ j4) & 15) * 4;   // swizzled d-block column
            float p[4][4], vv[4][4];
            #pragma unroll
            for (int ii = 0; ii < 4; ii++) {
                float4 pr = *(const float4*)&Ps[ty * 4 + ii][j4 * 4];
                p[ii][0] = pr.x; p[ii][1] = pr.y; p[ii][2] = pr.z; p[ii][3] = pr.w;
            }
            #pragma unroll
            for (int jj = 0; jj < 4; jj++) {
                float4 vr = *(const float4*)&KV[j4 * 4 + jj][sw];
                vv[jj][0] = vr.x; vv[jj][1] = vr.y; vv[jj][2] = vr.z; vv[jj][3] = vr.w;
            }
            #pragma unroll
            for (int ii = 0; ii < 4; ii++)
                #pragma unroll
                for (int jj = 0; jj < 4; jj++)
                    #pragma unroll
                    for (int dd = 0; dd < 4; dd++)
                        Ot[ii][dd] += p[ii][jj] * vv[jj][dd];
        }
        __syncthreads();   // KV + Ps free for next tile
    }

    // Epilogue: O[d][n] = Ot[i][d] / l[i]; float4 over 4 consecutive i
    float rl[4];
    #pragma unroll
    for (int ii = 0; ii < 4; ii++) rl[ii] = 1.f / l_i[ii];
    #pragma unroll
    for (int dd = 0; dd < 4; dd++) {
        int d = tx * 4 + dd;
        float4 r;
        r.x = Ot[0][dd] * rl[0];
        r.y = Ot[1][dd] * rl[1];
        r.z = Ot[2][dd] * rl[2];
        r.w = Ot[3][dd] * rl[3];
        *(float4*)&Op[(size_t)d * NPIX + n0 + ty * 4] = r;
    }
}

// ---------------------------------------------------------------------------
extern "C" void kernel_launch(void* const* d_in, const int* in_sizes, int n_in,
                              void* d_out, int out_size)
{
    const float* x  = (const float*)d_in[0];
    const float* Wq = (const float*)d_in[1];
    const float* bq = (const float*)d_in[2];
    const float* Wk = (const float*)d_in[3];
    const float* bk = (const float*)d_in[4];
    const float* Wv = (const float*)d_in[5];
    const float* bv = (const float*)d_in[6];
    const float* Wo = (const float*)d_in[7];
    const float* bo = (const float*)d_in[8];
    float* out = (float*)d_out;

    float *gQ, *gK, *gV, *gA;
    cudaGetSymbolAddress((void**)&gQ, g_Q);
    cudaGetSymbolAddress((void**)&gK, g_K);
    cudaGetSymbolAddress((void**)&gV, g_V);
    cudaGetSymbolAddress((void**)&gA, g_AO);

    dim3 gemm_grid(NPIX / 128, DIM / 128, BATCH);   // (8, 4, 8)
    dim3 blk(256);

    const float qscale = 0.125f;   // 1/sqrt(64) folded into Q projection

    gemm512<<<gemm_grid, blk>>>(Wq, x, bq, nullptr, gQ, qscale);
    gemm512<<<gemm_grid, blk>>>(Wk, x, bk, nullptr, gK, 1.f);
    gemm512<<<gemm_grid, blk>>>(Wv, x, bv, nullptr, gV, 1.f);

    dim3 attn_grid(NPIX / 64, NH, BATCH);           // (16, 8, 8)
    attn64<<<attn_grid, blk>>>(gQ, gK, gV, gA);

    gemm512<<<gemm_grid, blk>>>(Wo, gA, bo, x, out, 1.f);
}